// round 1
// baseline (speedup 1.0000x reference)
#include <cuda_runtime.h>

#define Dv 512
#define Rv 64

// Scratch (device globals — no allocation allowed)
__device__ float g_Vt[Rv * Dv];   // Vt[r*Dv + d] : normalized reflection vectors, transposed
__device__ float g_G [Rv * Rv];   // Gram matrix G[k*Rv + j] = v_j . v_k
__device__ float g_A [Dv * Rv];   // WY factor A[d*Rv + r]   (x_out = x - (x A) V^T)

// ---------------------------------------------------------------------------
// K1: normalize each column u_r of params (D,R) -> g_Vt[r][*]
// ---------------------------------------------------------------------------
__global__ void k_norm(const float* __restrict__ P) {
    int r = blockIdx.x;            // 0..63
    int t = threadIdx.x;           // 256 threads
    __shared__ float red[256];
    float s = 0.f;
    for (int d = t; d < Dv; d += 256) {
        float v = P[d * Rv + r];
        s += v * v;
    }
    red[t] = s;
    __syncthreads();
    for (int o = 128; o > 0; o >>= 1) {
        if (t < o) red[t] += red[t + o];
        __syncthreads();
    }
    float rin = rsqrtf(red[0]);
    for (int d = t; d < Dv; d += 256) {
        g_Vt[r * Dv + d] = P[d * Rv + r] * rin;
    }
}

// ---------------------------------------------------------------------------
// K2: Gram matrix G[k][j] = <v_j, v_k>. One block per k, warp-per-j, both
// operands lane-contiguous through g_Vt.
// ---------------------------------------------------------------------------
__global__ void k_gram() {
    int k    = blockIdx.x;
    int w    = threadIdx.x >> 5;
    int lane = threadIdx.x & 31;
    for (int j = w; j < Rv; j += 8) {
        float s = 0.f;
        for (int d = lane; d < Dv; d += 32)
            s += g_Vt[j * Dv + d] * g_Vt[k * Dv + d];
        #pragma unroll
        for (int o = 16; o; o >>= 1) s += __shfl_down_sync(0xFFFFFFFFu, s, o);
        if (lane == 0) g_G[k * Rv + j] = s;
    }
}

// ---------------------------------------------------------------------------
// K3: WY recurrence  a_k = 2 (v_k - sum_{j<k} a_j * G[k][j]).
// One block, 512 threads; thread d owns row d of A entirely in registers
// (loops fully unrolled so indexing is compile-time -> no local spills).
// ---------------------------------------------------------------------------
__global__ __launch_bounds__(512) void k_recur() {
    __shared__ float sG[Rv * Rv];
    int t = threadIdx.x;           // = d
    for (int idx = t; idx < Rv * Rv; idx += 512) sG[idx] = g_G[idx];
    __syncthreads();

    float Arow[Rv];
    #pragma unroll
    for (int k = 0; k < Rv; k++) {
        float vk  = g_Vt[k * Dv + t];
        float acc = 0.f;
        #pragma unroll
        for (int j = 0; j < Rv; j++)
            if (j < k) acc += Arow[j] * sG[k * Rv + j];
        float val = 2.f * (vk - acc);
        #pragma unroll
        for (int j = 0; j < Rv; j++)
            if (j == k) Arow[j] = val;
    }
    #pragma unroll
    for (int k = 0; k < Rv; k++) g_A[t * Rv + k] = Arow[k];
}

// ---------------------------------------------------------------------------
// Main fused kernel: per block, 16 rows of x.
//   stage 1: Y[i][r] = sum_d sx[i][d] * A[d][r]     (thread = (row, 4 r's))
//   stage 2: out[i][d] = sx[i][d] - sum_r Y[i][r] * Vt[r][d]
//            (thread owns 2 d-columns x 16 rows in registers)
// ---------------------------------------------------------------------------
#define TILE_ROWS 16
#define SX_LD (Dv + 4)   // pad: kills 2-way LDS bank conflict in stage 1

__global__ __launch_bounds__(256) void k_main(const float* __restrict__ x,
                                              float* __restrict__ out,
                                              int B) {
    __shared__ float sx[TILE_ROWS][SX_LD];
    __shared__ float sY[TILE_ROWS][Rv + 1];

    int rowBase = blockIdx.x * TILE_ROWS;
    int t = threadIdx.x;
    int rows = B - rowBase;
    if (rows > TILE_ROWS) rows = TILE_ROWS;

    // ---- load x tile (float4, coalesced) ----
    if (rows == TILE_ROWS) {
        const float4* xv = (const float4*)(x + (size_t)rowBase * Dv);
        for (int idx = t; idx < TILE_ROWS * (Dv / 4); idx += 256) {
            int row = idx >> 7;          // /128
            int col = idx & 127;
            float4 v = xv[row * (Dv / 4) + col];
            float4* dst = (float4*)(&sx[row][0]) + col;
            *dst = v;
        }
    } else {
        for (int idx = t; idx < TILE_ROWS * Dv; idx += 256) {
            int row = idx / Dv, col = idx % Dv;
            sx[row][col] = (row < rows) ? x[(size_t)(rowBase + row) * Dv + col] : 0.f;
        }
    }
    __syncthreads();

    // ---- stage 1: Y = x_tile @ A ----
    {
        int i  = t >> 4;            // row 0..15
        int r0 = (t & 15) << 2;     // 4 consecutive r
        float ax = 0.f, ay = 0.f, az = 0.f, aw = 0.f;
        #pragma unroll 8
        for (int d = 0; d < Dv; d++) {
            float  xs = sx[i][d];
            float4 a  = *(const float4*)&g_A[d * Rv + r0];
            ax = fmaf(xs, a.x, ax);
            ay = fmaf(xs, a.y, ay);
            az = fmaf(xs, a.z, az);
            aw = fmaf(xs, a.w, aw);
        }
        sY[i][r0 + 0] = ax;
        sY[i][r0 + 1] = ay;
        sY[i][r0 + 2] = az;
        sY[i][r0 + 3] = aw;
    }
    __syncthreads();

    // ---- stage 2: out = x_tile - Y @ V^T ----
    {
        int d0 = t;          // 0..255
        int d1 = t + 256;    // 256..511
        float o0[TILE_ROWS], o1[TILE_ROWS];
        #pragma unroll
        for (int ii = 0; ii < TILE_ROWS; ii++) {
            o0[ii] = sx[ii][d0];
            o1[ii] = sx[ii][d1];
        }
        for (int r = 0; r < Rv; r++) {
            float v0 = g_Vt[r * Dv + d0];
            float v1 = g_Vt[r * Dv + d1];
            #pragma unroll
            for (int ii = 0; ii < TILE_ROWS; ii++) {
                float y = sY[ii][r];
                o0[ii] = fmaf(-y, v0, o0[ii]);
                o1[ii] = fmaf(-y, v1, o1[ii]);
            }
        }
        #pragma unroll
        for (int ii = 0; ii < TILE_ROWS; ii++) {
            if (ii < rows) {
                out[(size_t)(rowBase + ii) * Dv + d0] = o0[ii];
                out[(size_t)(rowBase + ii) * Dv + d1] = o1[ii];
            }
        }
    }
}

// sldj passthrough
__global__ void k_copy(const float* __restrict__ s, float* __restrict__ o, int n) {
    int i = blockIdx.x * 256 + threadIdx.x;
    if (i < n) o[i] = s[i];
}

extern "C" void kernel_launch(void* const* d_in, const int* in_sizes, int n_in,
                              void* d_out, int out_size) {
    const float* x    = (const float*)d_in[0];   // (B, D)
    const float* sldj = (const float*)d_in[1];   // (B,)
    const float* P    = (const float*)d_in[2];   // (D, R)

    int BD = in_sizes[0];
    int Bn = in_sizes[1];
    (void)n_in;

    float* out = (float*)d_out;

    // Precompute WY factors (tiny; graph-capturable, deterministic)
    k_norm <<<Rv, 256>>>(P);
    k_gram <<<Rv, 256>>>();
    k_recur<<<1, 512>>>();

    // Main fused pass
    int nblocks = (Bn + TILE_ROWS - 1) / TILE_ROWS;
    k_main<<<nblocks, 256>>>(x, out, Bn);

    // sldj passthrough if the output buffer holds it
    if (out_size >= BD + Bn) {
        k_copy<<<(Bn + 255) / 256, 256>>>(sldj, out + BD, Bn);
    }
}

// round 3
// speedup vs baseline: 1.8992x; 1.8992x over previous
#include <cuda_runtime.h>
#include <cuda_bf16.h>
#include <cstdint>

#define Dv 512
#define Rv 64
#define TM 128
#define STRIDE 144            // smem row stride in bytes (72 bf16) -> conflict-free ldmatrix
#define NTHREADS 256

// ---------------------------------------------------------------------------
// Device scratch (no allocations allowed)
// ---------------------------------------------------------------------------
__device__ float g_Vt[Rv * Dv];   // normalized reflections, [r][d]
__device__ float g_G [Rv * Rv];
__device__ float g_A [Dv * Rv];   // WY factor, [d][r]
// Pre-packed bf16 hi/lo operand tiles, padded rows of 72 bf16 (144B)
__device__ __align__(16) __nv_bfloat16 g_Abh[8 * 64 * 72];   // chunk c: [r=64][kk=64(+pad)]
__device__ __align__(16) __nv_bfloat16 g_Abl[8 * 64 * 72];
__device__ __align__(16) __nv_bfloat16 g_Vbh[4 * 128 * 72];  // n-chunk j: [d=128][r=64(+pad)]
__device__ __align__(16) __nv_bfloat16 g_Vbl[4 * 128 * 72];

// ---------------------------------------------------------------------------
// Helpers
// ---------------------------------------------------------------------------
__device__ __forceinline__ uint32_t smem_to_u32(const void* p) {
    uint32_t a;
    asm("{ .reg .u64 t; cvta.to.shared.u64 t, %1; cvt.u32.u64 %0, t; }" : "=r"(a) : "l"(p));
    return a;
}
__device__ __forceinline__ void ldsm4(uint32_t* r, uint32_t addr) {
    asm volatile("ldmatrix.sync.aligned.m8n8.x4.shared.b16 {%0,%1,%2,%3}, [%4];"
                 : "=r"(r[0]), "=r"(r[1]), "=r"(r[2]), "=r"(r[3]) : "r"(addr));
}
__device__ __forceinline__ void mma16816(float* c, const uint32_t* a,
                                         uint32_t b0, uint32_t b1) {
    asm volatile("mma.sync.aligned.m16n8k16.row.col.f32.bf16.bf16.f32 "
                 "{%0,%1,%2,%3}, {%4,%5,%6,%7}, {%8,%9}, {%0,%1,%2,%3};"
                 : "+f"(c[0]), "+f"(c[1]), "+f"(c[2]), "+f"(c[3])
                 : "r"(a[0]), "r"(a[1]), "r"(a[2]), "r"(a[3]), "r"(b0), "r"(b1));
}
__device__ __forceinline__ void sts128(uint32_t a, uint32_t x, uint32_t y,
                                       uint32_t z, uint32_t w) {
    asm volatile("st.shared.v4.b32 [%0], {%1,%2,%3,%4};"
                 :: "r"(a), "r"(x), "r"(y), "r"(z), "r"(w) : "memory");
}
__device__ __forceinline__ void sts128v(uint32_t a, float4 v) {
    sts128(a, __float_as_uint(v.x), __float_as_uint(v.y),
           __float_as_uint(v.z), __float_as_uint(v.w));
}
__device__ __forceinline__ void sts32(uint32_t a, uint32_t v) {
    asm volatile("st.shared.b32 [%0], %1;" :: "r"(a), "r"(v) : "memory");
}
// pack two floats -> bf16x2 (f0 in low half)
__device__ __forceinline__ uint32_t cvt2(float f0, float f1) {
    uint32_t r;
    asm("cvt.rn.bf16x2.f32 %0, %1, %2;" : "=r"(r) : "f"(f1), "f"(f0));
    return r;
}
__device__ __forceinline__ float bl(uint32_t h) { return __uint_as_float(h << 16); }
__device__ __forceinline__ float bh(uint32_t h) { return __uint_as_float(h & 0xFFFF0000u); }

// ---------------------------------------------------------------------------
// Precompute kernels (tiny)
// ---------------------------------------------------------------------------
__global__ void k_norm(const float* __restrict__ P) {
    int r = blockIdx.x, t = threadIdx.x;
    __shared__ float red[256];
    float s = 0.f;
    for (int d = t; d < Dv; d += 256) { float v = P[d * Rv + r]; s += v * v; }
    red[t] = s; __syncthreads();
    for (int o = 128; o > 0; o >>= 1) { if (t < o) red[t] += red[t + o]; __syncthreads(); }
    float rin = rsqrtf(red[0]);
    for (int d = t; d < Dv; d += 256) g_Vt[r * Dv + d] = P[d * Rv + r] * rin;
}

__global__ void k_gram() {
    int k = blockIdx.x, w = threadIdx.x >> 5, lane = threadIdx.x & 31;
    for (int j = w; j < Rv; j += 8) {
        float s = 0.f;
        for (int d = lane; d < Dv; d += 32) s += g_Vt[j * Dv + d] * g_Vt[k * Dv + d];
        #pragma unroll
        for (int o = 16; o; o >>= 1) s += __shfl_down_sync(0xFFFFFFFFu, s, o);
        if (lane == 0) g_G[k * Rv + j] = s;
    }
}

__global__ __launch_bounds__(512) void k_recur() {
    __shared__ float sG[Rv * Rv];
    int t = threadIdx.x;
    for (int i = t; i < Rv * Rv; i += 512) sG[i] = g_G[i];
    __syncthreads();
    float Arow[Rv];
    #pragma unroll
    for (int k = 0; k < Rv; k++) {
        float vk = g_Vt[k * Dv + t], acc = 0.f;
        #pragma unroll
        for (int j = 0; j < Rv; j++) if (j < k) acc += Arow[j] * sG[k * Rv + j];
        float val = 2.f * (vk - acc);
        #pragma unroll
        for (int j = 0; j < Rv; j++) if (j == k) Arow[j] = val;
    }
    #pragma unroll
    for (int k = 0; k < Rv; k++) g_A[t * Rv + k] = Arow[k];
}

// Pack A as B-operand tiles: chunk c -> [r][kk] rows (k along row), padded 72
__global__ void k_packA() {
    int c = blockIdx.x;
    for (int idx = threadIdx.x; idx < 64 * 64; idx += 256) {
        int r = idx >> 6, kk = idx & 63;
        float v = g_A[(c * 64 + kk) * Rv + r];
        __nv_bfloat16 h = __float2bfloat16_rn(v);
        float lo = v - __bfloat162float(h);
        int o = c * 4608 + r * 72 + kk;
        g_Abh[o] = h;
        g_Abl[o] = __float2bfloat16_rn(lo);
    }
}

// Pack V as B-operand tiles: n-chunk j -> [d local 128][r] rows, padded 72
__global__ void k_packV() {
    int j = blockIdx.x;
    for (int idx = threadIdx.x; idx < 128 * 64; idx += 256) {
        int n = idx >> 6, r = idx & 63;
        float v = g_Vt[r * Dv + j * 128 + n];
        __nv_bfloat16 h = __float2bfloat16_rn(v);
        float lo = v - __bfloat162float(h);
        int o = j * 9216 + n * 72 + r;
        g_Vbh[o] = h;
        g_Vbl[o] = __float2bfloat16_rn(lo);
    }
}

// ---------------------------------------------------------------------------
// Main fused kernel: out[m0:m0+128, :] = X - (X A) V^T  via mma.sync bf16 3-split
// smem layout:
//   [0,      18432)  Xh  (later Yh)       128 rows x 144B
//   [18432,  36864)  Xl  (later Yl)
//   [36864,  46080)  Ah   64 rows x 144B
//   [46080,  55296)  Al
//   [55296,  73728)  Vh  128 rows x 144B
//   [73728,  92160)  Vl
// ---------------------------------------------------------------------------
#define SMEM_BYTES 92160

__global__ __launch_bounds__(NTHREADS) void k_gemm(const float* __restrict__ x,
                                                   float* __restrict__ out) {
    extern __shared__ char smem[];
    uint32_t sb  = smem_to_u32(smem);
    const uint32_t sXh = sb;
    const uint32_t sXl = sb + 18432;
    const uint32_t sAh = sb + 36864;
    const uint32_t sAl = sb + 46080;
    const uint32_t sVh = sb + 55296;
    const uint32_t sVl = sb + 73728;

    int tid = threadIdx.x, wid = tid >> 5, lane = tid & 31;
    int m0 = blockIdx.x * TM;
    int mw = wid << 4;                        // warp's first row (16 rows/warp)

    // ldmatrix lane addressing (x4): row = base + (lane&15), col8 = (lane>>4)*8
    uint32_t lrow = lane & 15;
    uint32_t lcolb = ((lane >> 4) << 3) * 2;  // byte offset of 8-col group
    uint32_t aoff = (mw + lrow) * STRIDE + lcolb;   // A-operand (X rows / Y rows)
    uint32_t boff = lrow * STRIDE + lcolb;          // B-operand tiles

    float acc[8][4];
    #pragma unroll
    for (int i = 0; i < 8; i++)
        acc[i][0] = acc[i][1] = acc[i][2] = acc[i][3] = 0.f;

    // ================= Phase 1: Y = X A  (8 k-chunks of 64) =================
    for (int c = 0; c < 8; c++) {
        __syncthreads();
        // stage A chunk (pre-packed, pre-padded): 576 float4 each for hi/lo
        const float4* gAh = (const float4*)(g_Abh + c * 4608);
        const float4* gAl = (const float4*)(g_Abl + c * 4608);
        for (int i = tid; i < 576; i += NTHREADS) {
            sts128v(sAh + i * 16, gAh[i]);
            sts128v(sAl + i * 16, gAl[i]);
        }
        // convert X chunk to bf16 hi/lo: 128 rows x 8 groups of 8 floats
        for (int it = tid; it < 1024; it += NTHREADS) {
            int row = it >> 3, g = it & 7;
            const float4* xp = (const float4*)(x + (size_t)(m0 + row) * Dv + (c << 6) + (g << 3));
            float4 v0 = xp[0], v1 = xp[1];
            float f[8] = {v0.x, v0.y, v0.z, v0.w, v1.x, v1.y, v1.z, v1.w};
            uint32_t H[4], L[4];
            #pragma unroll
            for (int p = 0; p < 4; p++) {
                float f0 = f[2 * p], f1 = f[2 * p + 1];
                uint32_t h = cvt2(f0, f1);
                H[p] = h;
                L[p] = cvt2(f0 - bl(h), f1 - bh(h));
            }
            uint32_t ad = row * STRIDE + g * 16;
            sts128(sXh + ad, H[0], H[1], H[2], H[3]);
            sts128(sXl + ad, L[0], L[1], L[2], L[3]);
        }
        __syncthreads();

        #pragma unroll
        for (int ks = 0; ks < 4; ks++) {
            uint32_t ah[4], al[4];
            ldsm4(ah, sXh + aoff + ks * 32);
            ldsm4(al, sXl + aoff + ks * 32);
            #pragma unroll
            for (int p = 0; p < 4; p++) {     // pairs of n-tiles
                uint32_t bhr[4], blr[4];
                ldsm4(bhr, sAh + boff + p * (16 * STRIDE) + ks * 32);
                ldsm4(blr, sAl + boff + p * (16 * STRIDE) + ks * 32);
                mma16816(acc[2 * p],     ah, bhr[0], bhr[2]);
                mma16816(acc[2 * p],     ah, blr[0], blr[2]);
                mma16816(acc[2 * p],     al, bhr[0], bhr[2]);
                mma16816(acc[2 * p + 1], ah, bhr[1], bhr[3]);
                mma16816(acc[2 * p + 1], ah, blr[1], blr[3]);
                mma16816(acc[2 * p + 1], al, bhr[1], bhr[3]);
            }
        }
    }

    // ============ Y -> smem (split bf16), reuse X region (own rows) =========
    {
        uint32_t r0 = mw + (lane >> 2);
        uint32_t cbyte = ((lane & 3) << 1) * 2;
        #pragma unroll
        for (int nt = 0; nt < 8; nt++) {
            uint32_t colb = nt * 16 + cbyte;
            float f0 = acc[nt][0], f1 = acc[nt][1], f2 = acc[nt][2], f3 = acc[nt][3];
            uint32_t h01 = cvt2(f0, f1);
            uint32_t l01 = cvt2(f0 - bl(h01), f1 - bh(h01));
            uint32_t h23 = cvt2(f2, f3);
            uint32_t l23 = cvt2(f2 - bl(h23), f3 - bh(h23));
            sts32(sXh + r0 * STRIDE + colb, h01);
            sts32(sXl + r0 * STRIDE + colb, l01);
            sts32(sXh + (r0 + 8) * STRIDE + colb, h23);
            sts32(sXl + (r0 + 8) * STRIDE + colb, l23);
        }
    }
    __syncwarp();

    // ================= Phase 2: Z = Y V^T, out = X - Z  (4 n-chunks) ========
    for (int j = 0; j < 4; j++) {
        __syncthreads();      // prior iteration's mma reads of V done
        const float4* gVh = (const float4*)(g_Vbh + j * 9216);
        const float4* gVl = (const float4*)(g_Vbl + j * 9216);
        for (int i = tid; i < 1152; i += NTHREADS) {
            sts128v(sVh + i * 16, gVh[i]);
            sts128v(sVl + i * 16, gVl[i]);
        }
        __syncthreads();

        float z[16][4];
        #pragma unroll
        for (int i = 0; i < 16; i++)
            z[i][0] = z[i][1] = z[i][2] = z[i][3] = 0.f;

        #pragma unroll
        for (int ks = 0; ks < 4; ks++) {
            uint32_t yh[4], yl[4];
            ldsm4(yh, sXh + aoff + ks * 32);
            ldsm4(yl, sXl + aoff + ks * 32);
            #pragma unroll
            for (int p = 0; p < 8; p++) {
                uint32_t bhr[4], blr[4];
                ldsm4(bhr, sVh + boff + p * (16 * STRIDE) + ks * 32);
                ldsm4(blr, sVl + boff + p * (16 * STRIDE) + ks * 32);
                mma16816(z[2 * p],     yh, bhr[0], bhr[2]);
                mma16816(z[2 * p],     yh, blr[0], blr[2]);
                mma16816(z[2 * p],     yl, bhr[0], bhr[2]);
                mma16816(z[2 * p + 1], yh, bhr[1], bhr[3]);
                mma16816(z[2 * p + 1], yh, blr[1], blr[3]);
                mma16816(z[2 * p + 1], yl, bhr[1], bhr[3]);
            }
        }

        // epilogue: out = x - z (direct, fragment-mapped float2)
        int r0 = m0 + mw + (lane >> 2);
        const float* x0 = x + (size_t)r0 * Dv;
        const float* x1 = x0 + 8 * Dv;
        float* o0 = out + (size_t)r0 * Dv;
        float* o1 = o0 + 8 * Dv;
        int cbase = (j << 7) + ((lane & 3) << 1);
        #pragma unroll
        for (int nt = 0; nt < 16; nt++) {
            int cc = cbase + nt * 8;
            float2 a0 = *(const float2*)(x0 + cc);
            float2 a1 = *(const float2*)(x1 + cc);
            float2 w0 = make_float2(a0.x - z[nt][0], a0.y - z[nt][1]);
            float2 w1 = make_float2(a1.x - z[nt][2], a1.y - z[nt][3]);
            *(float2*)(o0 + cc) = w0;
            *(float2*)(o1 + cc) = w1;
        }
    }
}

// sldj passthrough
__global__ void k_copy(const float* __restrict__ s, float* __restrict__ o, int n) {
    int i = blockIdx.x * 256 + threadIdx.x;
    if (i < n) o[i] = s[i];
}

extern "C" void kernel_launch(void* const* d_in, const int* in_sizes, int n_in,
                              void* d_out, int out_size) {
    const float* x    = (const float*)d_in[0];   // (B, D)
    const float* sldj = (const float*)d_in[1];   // (B,)
    const float* P    = (const float*)d_in[2];   // (D, R)
    int BD = in_sizes[0];
    int Bn = in_sizes[1];
    (void)n_in;
    float* out = (float*)d_out;

    // Tiny precompute: normalize -> Gram -> WY recurrence -> packed bf16 tiles
    k_norm <<<Rv, 256>>>(P);
    k_gram <<<Rv, 256>>>();
    k_recur<<<1, 512>>>();
    k_packA<<<8, 256>>>();
    k_packV<<<4, 256>>>();

    cudaFuncSetAttribute(k_gemm, cudaFuncAttributeMaxDynamicSharedMemorySize, SMEM_BYTES);
    k_gemm<<<Bn / TM, NTHREADS, SMEM_BYTES>>>(x, out);

    if (out_size >= BD + Bn) {
        k_copy<<<(Bn + 255) / 256, 256>>>(sldj, out + BD, Bn);
    }
}

// round 4
// speedup vs baseline: 2.5729x; 1.3547x over previous
#include <cuda_runtime.h>
#include <cuda_bf16.h>
#include <cstdint>

#define Dv 512
#define Rv 64
#define TM 128
#define NTHREADS 256

// ---------------------------------------------------------------------------
// Device scratch
// ---------------------------------------------------------------------------
__device__ float g_Vt[Rv * Dv];   // normalized reflections, [r][d]
__device__ float g_G [Rv * Rv];   // Gram matrix
// Pre-packed bf16 hi/lo operand tiles, 128B rows, SW128-swizzled (final form)
__device__ __align__(16) __nv_bfloat16 g_Abh[8 * 64 * 64];   // chunk c: [r][kk]
__device__ __align__(16) __nv_bfloat16 g_Abl[8 * 64 * 64];
__device__ __align__(16) __nv_bfloat16 g_Vbh[4 * 128 * 64];  // n-chunk j: [n][r]
__device__ __align__(16) __nv_bfloat16 g_Vbl[4 * 128 * 64];

// ---------------------------------------------------------------------------
// Helpers
// ---------------------------------------------------------------------------
#define SWZ(o) ((o) ^ (((o) >> 3) & 0x70))

__device__ __forceinline__ uint32_t smem_to_u32(const void* p) {
    uint32_t a;
    asm("{ .reg .u64 t; cvta.to.shared.u64 t, %1; cvt.u32.u64 %0, t; }" : "=r"(a) : "l"(p));
    return a;
}
__device__ __forceinline__ void ldsm4(uint32_t* r, uint32_t addr) {
    asm volatile("ldmatrix.sync.aligned.m8n8.x4.shared.b16 {%0,%1,%2,%3}, [%4];"
                 : "=r"(r[0]), "=r"(r[1]), "=r"(r[2]), "=r"(r[3]) : "r"(addr));
}
__device__ __forceinline__ void mma16816(float* c, const uint32_t* a,
                                         uint32_t b0, uint32_t b1) {
    asm volatile("mma.sync.aligned.m16n8k16.row.col.f32.bf16.bf16.f32 "
                 "{%0,%1,%2,%3}, {%4,%5,%6,%7}, {%8,%9}, {%0,%1,%2,%3};"
                 : "+f"(c[0]), "+f"(c[1]), "+f"(c[2]), "+f"(c[3])
                 : "r"(a[0]), "r"(a[1]), "r"(a[2]), "r"(a[3]), "r"(b0), "r"(b1));
}
__device__ __forceinline__ void sts128(uint32_t a, uint32_t x, uint32_t y,
                                       uint32_t z, uint32_t w) {
    asm volatile("st.shared.v4.b32 [%0], {%1,%2,%3,%4};"
                 :: "r"(a), "r"(x), "r"(y), "r"(z), "r"(w) : "memory");
}
__device__ __forceinline__ void sts32(uint32_t a, uint32_t v) {
    asm volatile("st.shared.b32 [%0], %1;" :: "r"(a), "r"(v) : "memory");
}
__device__ __forceinline__ float4 lds128(uint32_t a) {
    float4 v;
    asm volatile("ld.shared.v4.f32 {%0,%1,%2,%3}, [%4];"
                 : "=f"(v.x), "=f"(v.y), "=f"(v.z), "=f"(v.w) : "r"(a));
    return v;
}
__device__ __forceinline__ void cpasync16(uint32_t dst, const void* src) {
    asm volatile("cp.async.cg.shared.global [%0], [%1], 16;"
                 :: "r"(dst), "l"(src) : "memory");
}
#define CP_COMMIT() asm volatile("cp.async.commit_group;" ::: "memory")
#define CP_WAIT(N)  asm volatile("cp.async.wait_group %0;" :: "n"(N) : "memory")

// pack two floats -> bf16x2 (f0 low)
__device__ __forceinline__ uint32_t cvt2(float f0, float f1) {
    uint32_t r;
    asm("cvt.rn.bf16x2.f32 %0, %1, %2;" : "=r"(r) : "f"(f1), "f"(f0));
    return r;
}
__device__ __forceinline__ float bl(uint32_t h) { return __uint_as_float(h << 16); }
__device__ __forceinline__ float bh(uint32_t h) { return __uint_as_float(h & 0xFFFF0000u); }

// ---------------------------------------------------------------------------
// Precompute 1: normalize columns -> g_Vt
// ---------------------------------------------------------------------------
__global__ void k_norm(const float* __restrict__ P) {
    int r = blockIdx.x, t = threadIdx.x;
    __shared__ float red[256];
    float s = 0.f;
    for (int d = t; d < Dv; d += 256) { float v = P[d * Rv + r]; s += v * v; }
    red[t] = s; __syncthreads();
    for (int o = 128; o > 0; o >>= 1) { if (t < o) red[t] += red[t + o]; __syncthreads(); }
    float rin = rsqrtf(red[0]);
    for (int d = t; d < Dv; d += 256) g_Vt[r * Dv + d] = P[d * Rv + r] * rin;
}

// ---------------------------------------------------------------------------
// Precompute 2: Gram matrix; blocks 0..3 additionally pack V n-chunk j=blockIdx
// ---------------------------------------------------------------------------
__global__ void k_gram_packV() {
    __shared__ float sV[64][129];
    int k = blockIdx.x, tid = threadIdx.x, w = tid >> 5, lane = tid & 31;
    for (int j = w; j < Rv; j += 8) {
        float s = 0.f;
        for (int d = lane; d < Dv; d += 32) s += g_Vt[j * Dv + d] * g_Vt[k * Dv + d];
        #pragma unroll
        for (int o = 16; o; o >>= 1) s += __shfl_down_sync(0xFFFFFFFFu, s, o);
        if (lane == 0) g_G[k * Rv + j] = s;
    }
    if (k < 4) {
        int j = k;
        for (int idx = tid; idx < 8192; idx += 256) {
            int r = idx >> 7, n = idx & 127;
            sV[r][n] = g_Vt[r * Dv + j * 128 + n];
        }
        __syncthreads();
        for (int idx = tid; idx < 8192; idx += 256) {
            int n = idx >> 6, r = idx & 63;
            float v = sV[r][n];
            __nv_bfloat16 h = __float2bfloat16_rn(v);
            float lo = v - __bfloat162float(h);
            uint32_t off = j * 16384 + SWZ((uint32_t)(n * 128 + r * 2));
            *(__nv_bfloat16*)((char*)g_Vbh + off) = h;
            *(__nv_bfloat16*)((char*)g_Vbl + off) = __float2bfloat16_rn(lo);
        }
    }
}

// ---------------------------------------------------------------------------
// Precompute 3: WY recurrence + pack A (smem transpose per chunk)
// ---------------------------------------------------------------------------
__global__ __launch_bounds__(512) void k_recur_packA() {
    __shared__ float sG[Rv * Rv];
    __shared__ float sT[64][65];
    int t = threadIdx.x;
    for (int i = t; i < Rv * Rv; i += 512) sG[i] = g_G[i];
    __syncthreads();
    float Arow[Rv];
    float acc4[4];
    #pragma unroll
    for (int k = 0; k < Rv; k++) {
        float vk = g_Vt[k * Dv + t];
        acc4[0] = acc4[1] = acc4[2] = acc4[3] = 0.f;
        #pragma unroll
        for (int j = 0; j < Rv; j++)
            if (j < k) acc4[j & 3] += Arow[j] * sG[k * Rv + j];
        float val = 2.f * (vk - ((acc4[0] + acc4[1]) + (acc4[2] + acc4[3])));
        #pragma unroll
        for (int j = 0; j < Rv; j++) if (j == k) Arow[j] = val;
    }
    // pack chunks: A'[c][r][kk] = A[d = c*64+kk][r]
    for (int c = 0; c < 8; c++) {
        __syncthreads();
        if ((t >> 6) == c) {
            int kk = t & 63;
            #pragma unroll
            for (int r = 0; r < Rv; r++) sT[kk][r] = Arow[r];
        }
        __syncthreads();
        for (int idx = t; idx < 4096; idx += 512) {
            int r = idx >> 6, kk = idx & 63;
            float v = sT[kk][r];
            __nv_bfloat16 h = __float2bfloat16_rn(v);
            float lo = v - __bfloat162float(h);
            uint32_t off = c * 8192 + SWZ((uint32_t)(r * 128 + kk * 2));
            *(__nv_bfloat16*)((char*)g_Abh + off) = h;
            *(__nv_bfloat16*)((char*)g_Abl + off) = __float2bfloat16_rn(lo);
        }
    }
}

// ---------------------------------------------------------------------------
// Main kernel. smem (96KB, 2 CTA/SM):
//   [0,     32768)  stage: raw fp32 X chunk (cp.async) / V ping (phase 2)
//   [32768, 49152)  Xh (-> Yh)
//   [49152, 65536)  Xl (-> Yl)
//   [65536, 81920)  A buf0 (hi 8K + lo 8K) / V pong hi
//   [81920, 98304)  A buf1 (hi 8K + lo 8K) / V pong lo
// ---------------------------------------------------------------------------
#define OFF_STAGE 0
#define OFF_XH    32768
#define OFF_XL    49152
#define OFF_A0    65536
#define OFF_A1    81920
#define SMEM_BYTES 98304

__global__ __launch_bounds__(NTHREADS, 2) void k_gemm(const float* __restrict__ x,
                                                      float* __restrict__ out,
                                                      const float* __restrict__ sldj,
                                                      float* __restrict__ outSldj) {
    extern __shared__ char smem[];
    uint32_t sb = smem_to_u32(smem);
    const uint32_t sStage = sb + OFF_STAGE;
    const uint32_t sXh = sb + OFF_XH;
    const uint32_t sXl = sb + OFF_XL;

    int tid = threadIdx.x, wid = tid >> 5, lane = tid & 31;
    int m0 = blockIdx.x * TM;
    int mw = wid << 4;

    // ldmatrix lane addressing
    uint32_t lrow = lane & 15;
    uint32_t lcolb = (lane >> 4) << 4;            // 0 or 16 bytes
    uint32_t xr = (lrow & 7) << 4;                // SW128 xor (same for A rows: mw mult of 16)
    uint32_t arowb = (mw + lrow) * 128;           // A-operand row byte base

    // cp.async issue lambdas (as plain code)
    // X chunk c -> stage (row-rotated 32B blocks: chunk' = i ^ ((r&7)<<1))
    auto issueX = [&](int c) {
        for (int idx = tid; idx < 2048; idx += NTHREADS) {
            int r = idx >> 4, i = idx & 15;
            uint32_t dst = sStage + r * 256 + (((uint32_t)(i * 16)) ^ ((r & 7) << 5));
            const char* src = (const char*)(x + (size_t)(m0 + r) * Dv + c * 64 + i * 4);
            cpasync16(dst, src);
        }
    };
    auto issueA = [&](int c, uint32_t buf) {
        const char* srch = (const char*)g_Abh + c * 8192;
        const char* srcl = (const char*)g_Abl + c * 8192;
        for (int idx = tid; idx < 512; idx += NTHREADS) {
            cpasync16(buf + idx * 16, srch + idx * 16);
            cpasync16(buf + 8192 + idx * 16, srcl + idx * 16);
        }
    };
    auto issueV = [&](int j, uint32_t bufh, uint32_t bufl) {
        const char* srch = (const char*)g_Vbh + j * 16384;
        const char* srcl = (const char*)g_Vbl + j * 16384;
        for (int idx = tid; idx < 1024; idx += NTHREADS) {
            cpasync16(bufh + idx * 16, srch + idx * 16);
            cpasync16(bufl + idx * 16, srcl + idx * 16);
        }
    };

    float acc[8][4];
    #pragma unroll
    for (int i = 0; i < 8; i++)
        acc[i][0] = acc[i][1] = acc[i][2] = acc[i][3] = 0.f;

    // prologue: prefetch chunk 0
    issueX(0); issueA(0, sb + OFF_A0); CP_COMMIT();

    // ================= Phase 1: Y = X A  (8 k-chunks of 64) =================
    for (int c = 0; c < 8; c++) {
        CP_WAIT(0);
        __syncthreads();
        // convert stage -> Xh/Xl (bf16 hi/lo, SW128)
        #pragma unroll
        for (int p = 0; p < 4; p++) {
            int it = tid + p * NTHREADS;
            int row = it >> 3, g = it & 7;
            uint32_t sa = sStage + row * 256 + (((uint32_t)(g * 32)) ^ ((row & 7) << 5));
            float4 v0 = lds128(sa);
            float4 v1 = lds128(sa + 16);
            float f[8] = {v0.x, v0.y, v0.z, v0.w, v1.x, v1.y, v1.z, v1.w};
            uint32_t H[4], L[4];
            #pragma unroll
            for (int q = 0; q < 4; q++) {
                uint32_t h = cvt2(f[2 * q], f[2 * q + 1]);
                H[q] = h;
                L[q] = cvt2(f[2 * q] - bl(h), f[2 * q + 1] - bh(h));
            }
            uint32_t ad = row * 128 + (((uint32_t)(g * 16)) ^ ((row & 7) << 4));
            sts128(sXh + ad, H[0], H[1], H[2], H[3]);
            sts128(sXl + ad, L[0], L[1], L[2], L[3]);
        }
        __syncthreads();
        // prefetch next chunk (overlaps MMA below)
        if (c < 7) {
            issueX(c + 1);
            issueA(c + 1, sb + ((c + 1) & 1 ? OFF_A1 : OFF_A0));
            CP_COMMIT();
        } else {
            // prefetch V(0) into stage (consumed; free)
            issueV(0, sStage, sStage + 16384);
            CP_COMMIT();
        }
        // MMA on chunk c
        uint32_t bufAh = sb + ((c & 1) ? OFF_A1 : OFF_A0);
        uint32_t bufAl = bufAh + 8192;
        #pragma unroll
        for (int ks = 0; ks < 4; ks++) {
            uint32_t ic = (lcolb + ks * 32) ^ xr;
            uint32_t ah[4], al[4];
            ldsm4(ah, sXh + arowb + ic);
            ldsm4(al, sXl + arowb + ic);
            #pragma unroll
            for (int p = 0; p < 4; p++) {
                uint32_t ro = (lrow + p * 16) * 128;
                uint32_t bhr[4], blr[4];
                ldsm4(bhr, bufAh + ro + ic);
                ldsm4(blr, bufAl + ro + ic);
                mma16816(acc[2 * p],     ah, bhr[0], bhr[2]);
                mma16816(acc[2 * p],     ah, blr[0], blr[2]);
                mma16816(acc[2 * p],     al, bhr[0], bhr[2]);
                mma16816(acc[2 * p + 1], ah, bhr[1], bhr[3]);
                mma16816(acc[2 * p + 1], ah, blr[1], blr[3]);
                mma16816(acc[2 * p + 1], al, bhr[1], bhr[3]);
            }
        }
    }
    __syncthreads();                 // all MMA(7) reads of A1 done
    issueV(1, sb + OFF_A0, sb + OFF_A1);   // V(1) -> pong
    CP_COMMIT();

    // ============ Y -> smem (split bf16), reuse X region (own rows) =========
    {
        uint32_t r0 = mw + (lane >> 2);
        uint32_t cbyte = (lane & 3) << 2;
        uint32_t x0 = (r0 & 7) << 4;         // same for r0 and r0+8
        #pragma unroll
        for (int nt = 0; nt < 8; nt++) {
            uint32_t colb = (nt * 16 + cbyte);
            float f0 = acc[nt][0], f1 = acc[nt][1], f2 = acc[nt][2], f3 = acc[nt][3];
            uint32_t h01 = cvt2(f0, f1);
            uint32_t l01 = cvt2(f0 - bl(h01), f1 - bh(h01));
            uint32_t h23 = cvt2(f2, f3);
            uint32_t l23 = cvt2(f2 - bl(h23), f3 - bh(h23));
            uint32_t sw = colb ^ x0;
            sts32(sXh + r0 * 128 + sw, h01);
            sts32(sXl + r0 * 128 + sw, l01);
            sts32(sXh + (r0 + 8) * 128 + sw, h23);
            sts32(sXl + (r0 + 8) * 128 + sw, l23);
        }
    }
    __syncwarp();

    // ================= Phase 2: Z = Y V^T, out = X - Z  (4 n-chunks) ========
    for (int j = 0; j < 4; j++) {
        if (j < 3) { CP_WAIT(1); } else { CP_WAIT(0); }
        __syncthreads();
        uint32_t bufVh = (j & 1) ? (sb + OFF_A0) : sStage;
        uint32_t bufVl = bufVh + 16384;

        float z[16][4];
        #pragma unroll
        for (int i = 0; i < 16; i++)
            z[i][0] = z[i][1] = z[i][2] = z[i][3] = 0.f;

        #pragma unroll
        for (int ks = 0; ks < 4; ks++) {
            uint32_t ic = (lcolb + ks * 32) ^ xr;
            uint32_t yh[4], yl[4];
            ldsm4(yh, sXh + arowb + ic);
            ldsm4(yl, sXl + arowb + ic);
            #pragma unroll
            for (int p = 0; p < 8; p++) {
                uint32_t ro = (lrow + p * 16) * 128;
                uint32_t bhr[4], blr[4];
                ldsm4(bhr, bufVh + ro + ic);
                ldsm4(blr, bufVl + ro + ic);
                mma16816(z[2 * p],     yh, bhr[0], bhr[2]);
                mma16816(z[2 * p],     yh, blr[0], blr[2]);
                mma16816(z[2 * p],     yl, bhr[0], bhr[2]);
                mma16816(z[2 * p + 1], yh, bhr[1], bhr[3]);
                mma16816(z[2 * p + 1], yh, blr[1], blr[3]);
                mma16816(z[2 * p + 1], yl, bhr[1], bhr[3]);
            }
        }
        __syncthreads();             // everyone done reading this V buffer
        if (j < 2) {                 // prefetch V(j+2) into the buffer just freed
            uint32_t nh = (j & 1) ? (sb + OFF_A0) : sStage;
            issueV(j + 2, nh, nh + 16384);
            CP_COMMIT();
        }

        // epilogue: out = x - z (fragment-mapped float2)
        int r0 = m0 + mw + (lane >> 2);
        const float* x0p = x + (size_t)r0 * Dv;
        const float* x1p = x0p + 8 * Dv;
        float* o0 = out + (size_t)r0 * Dv;
        float* o1 = o0 + 8 * Dv;
        int cbase = (j << 7) + ((lane & 3) << 1);
        #pragma unroll
        for (int nt = 0; nt < 16; nt++) {
            int cc = cbase + nt * 8;
            float2 a0 = *(const float2*)(x0p + cc);
            float2 a1 = *(const float2*)(x1p + cc);
            float2 w0 = make_float2(a0.x - z[nt][0], a0.y - z[nt][1]);
            float2 w1 = make_float2(a1.x - z[nt][2], a1.y - z[nt][3]);
            *(float2*)(o0 + cc) = w0;
            *(float2*)(o1 + cc) = w1;
        }
    }

    // sldj passthrough (folded)
    if (outSldj != nullptr && tid < TM) {
        outSldj[m0 + tid] = sldj[m0 + tid];
    }
}

extern "C" void kernel_launch(void* const* d_in, const int* in_sizes, int n_in,
                              void* d_out, int out_size) {
    const float* x    = (const float*)d_in[0];   // (B, D)
    const float* sldj = (const float*)d_in[1];   // (B,)
    const float* P    = (const float*)d_in[2];   // (D, R)
    int BD = in_sizes[0];
    int Bn = in_sizes[1];
    (void)n_in;
    float* out = (float*)d_out;
    float* osl = (out_size >= BD + Bn) ? (out + BD) : nullptr;

    k_norm       <<<Rv, 256>>>(P);
    k_gram_packV <<<Rv, 256>>>();
    k_recur_packA<<<1, 512>>>();

    cudaFuncSetAttribute(k_gemm, cudaFuncAttributeMaxDynamicSharedMemorySize, SMEM_BYTES);
    k_gemm<<<Bn / TM, NTHREADS, SMEM_BYTES>>>(x, out, sldj, osl);
}